// round 14
// baseline (speedup 1.0000x reference)
#include <cuda_runtime.h>
#include <math.h>
#include <stdint.h>

#define NSAMP  8
#define NEXP   256
#define NMARK  10
#define KBOUND 40
#define NEV    20
#define NTAB   2048

// overlapped-pair table: g_tab[ev][i] = { f(c_i), f(c_{i+1}) },  c_i = -1 + i*h
__device__ float2 g_tab[NEV * NTAB];   // 327 KB, L2-resident

// cos with explicit Cody-Waite reduction by 2*pi, then MUFU cos.
__device__ __forceinline__ float cos_cw(float t) {
    const float INV2PI   = 0.15915494309189535f;
    const float TWOPI_HI = 6.2831854820251465f;
    const float TWOPI_LO = -1.7484555e-07f;
    float k = rintf(t * INV2PI);
    float r = fmaf(-k, TWOPI_HI, t);
    r = fmaf(-k, TWOPI_LO, r);
    return __cosf(r);
}

// exact-path sum_m softplus (table build only)
__device__ __forceinline__ float total_intensity_reg(float c,
                                                     const float* __restrict__ c0,
                                                     const float* __restrict__ sc) {
    float lin = 0.0f, prod = 1.0f;
#pragma unroll
    for (int m = 0; m < NMARK; m++) {
        float x = fmaf(sc[m], c, c0[m]);
        lin += fmaxf(x, 0.0f);
        prod *= (1.0f + __expf(-fabsf(x)));
    }
    return lin + __logf(prod);
}

// table lookup with linear interpolation; c in [-1,1]
__device__ __forceinline__ float total_lookup(float c, const float2* __restrict__ tab) {
    float idx_f = (c + 1.0f) * ((float)(NTAB - 1) * 0.5f);
    int   i     = (int)idx_f;
    i = max(0, min(i, NTAB - 2));
    float frac  = idx_f - (float)i;
    float2 p = tab[i];
    return fmaf(frac, p.y - p.x, p.x);
}

__device__ __forceinline__ void cp_async16(void* smem_dst, const void* gmem_src) {
    unsigned saddr = (unsigned)__cvta_generic_to_shared(smem_dst);
    asm volatile("cp.async.cg.shared.global [%0], [%1], 16;\n"
                 :: "r"(saddr), "l"(gmem_src) : "memory");
}

// detect int64 vs int32 encoding of event_seq, return event id for `row`.
__device__ __forceinline__ int load_event(const int* __restrict__ ev_w,
                                          int row, int lane) {
    int a = 0;
    if (lane < NMARK) a = ev_w[2 * lane + 1] | ev_w[2 * (lane + NMARK) + 1];
    unsigned ball = __ballot_sync(0xffffffffu, a != 0);
    return (ball == 0u) ? ev_w[2 * row] : ev_w[row];
}

// ---- kernel T: build intensity table for all 20 event types ----
__global__ void __launch_bounds__(256) table_kernel(
    const float* __restrict__ emb,
    const float* __restrict__ scale,
    const float* __restrict__ bias)
{
    const int idx = blockIdx.x * 256 + threadIdx.x;   // 20*2048 entries
    const int ev  = idx / NTAB;
    const int i   = idx % NTAB;

    float c0[NMARK], sc[NMARK];
#pragma unroll
    for (int m = 0; m < NMARK; m++) {
        c0[m] = emb[ev * NMARK + m] + bias[m];
        sc[m] = scale[m];
    }
    const float h   = 2.0f / (float)(NTAB - 1);
    const float c0f = fmaf((float)i, h, -1.0f);
    const int   i1  = (i + 1 < NTAB) ? i + 1 : i;
    const float c1f = fmaf((float)i1, h, -1.0f);

    float2 v;
    v.x = total_intensity_reg(c0f, c0, sc);
    v.y = total_intensity_reg(c1f, c0, sc);
    g_tab[idx] = v;

    __threadfence();
    cudaTriggerProgrammaticLaunchCompletion();
}

// ---- sampler: 64-thr block per row + full-row cp.async unif staging ----
__global__ void __launch_bounds__(64, 22) sampler_kernel(
    const float* __restrict__ time_seq,
    const float* __restrict__ dt_seq,
    const int*   __restrict__ ev_w,
    const float* __restrict__ exp_raw,
    const float* __restrict__ unif,
    float* __restrict__ out_res,
    float* __restrict__ out_w,
    int write_w)
{
    const int row  = blockIdx.x;
    const int tid  = threadIdx.x;   // 0..63
    const int lane = tid & 31;
    const int warp = tid >> 5;      // 0..1

    __shared__ __align__(16) float s_unif[NSAMP * NEXP];  // 8 KB
    __shared__ __align__(16) float s_exr[NEXP];
    __shared__ __align__(16) float s_tot[NEXP];

    // ======== preamble: whole 8 KB unif row in flight immediately ========
    {
        const float* urow = unif + (size_t)row * (NSAMP * NEXP) + 32 * tid;
#pragma unroll
        for (int k = 0; k < 8; k++)
            cp_async16(&s_unif[32 * tid + 4 * k], urow + 4 * k);
        asm volatile("cp.async.commit_group;\n" ::: "memory");
    }
    // thread t owns candidates 4t..4t+3 (one coalesced LDG.128)
    const float4 ex4 = ((const float4*)(exp_raw + (size_t)row * NEXP))[tid];
    const float t0  = time_seq[row];
    const float dtv = dt_seq[row];
    const int   ev  = load_event(ev_w, row, lane);
    const float2* tab = g_tab + ev * NTAB;
    ((float4*)s_exr)[tid] = ex4;

    // ======== wait for table kernel ========
    cudaGridDependencySynchronize();

    // ---- boundary upper bound, redundant per warp (no barrier needed) ----
    float lam = total_lookup(cos_cw(fmaf(dtv, (float)lane * (1.0f / 39.0f), t0)), tab);
    if (lane < KBOUND - 32)
        lam = fmaxf(lam, total_lookup(
            cos_cw(fmaf(dtv, (float)(lane + 32) * (1.0f / 39.0f), t0)), tab));
#pragma unroll
    for (int o = 16; o; o >>= 1)
        lam = fmaxf(lam, __shfl_xor_sync(0xffffffffu, lam, o));
    const float upper = 1.5f * lam;   // OVER_SAMPLE_RATE; identical in both warps

    // ---- phase 1: 4 candidates per thread via table ----
    float4 tot4;
    tot4.x = total_lookup(cos_cw(t0 + __fdividef(ex4.x, upper)), tab);
    tot4.y = total_lookup(cos_cw(t0 + __fdividef(ex4.y, upper)), tab);
    tot4.z = total_lookup(cos_cw(t0 + __fdividef(ex4.z, upper)), tab);
    tot4.w = total_lookup(cos_cw(t0 + __fdividef(ex4.w, upper)), tab);
    ((float4*)s_tot)[tid] = tot4;

    asm volatile("cp.async.wait_group 0;\n" ::: "memory");
    __syncthreads();   // the only block barrier

    // ---- phase 2: warp w owns slots 4w..4w+3; all LDS.128, conflict-free ----
    const float4* pe = (const float4*)s_exr;
    const float4* pt = (const float4*)s_tot;
#pragma unroll
    for (int js = 0; js < 4; js++) {
        const int j = warp * 4 + js;
        const float4* su = (const float4*)(s_unif + j * NEXP);
        float m = INFINITY;
#pragma unroll
        for (int half = 0; half < 2; half++) {
            int q = 32 * half + lane;
            float4 u4 = su[q];
            float4 e4 = pe[q];
            float4 t4 = pt[q];
            if (u4.x * upper < t4.x) m = fminf(m, e4.x);
            if (u4.y * upper < t4.y) m = fminf(m, e4.y);
            if (u4.z * upper < t4.z) m = fminf(m, e4.z);
            if (u4.w * upper < t4.w) m = fminf(m, e4.w);
        }
#pragma unroll
        for (int o = 16; o; o >>= 1)
            m = fminf(m, __shfl_xor_sync(0xffffffffu, m, o));
        if (lane == 0) {
            // min over exr, then one divide == the winning candidate's ex bits
            float r = isinf(m) ? 5.0f : fminf(__fdividef(m, upper), 1e5f);
            out_res[row * NSAMP + j] = r;
            if (write_w) out_w[row * NSAMP + j] = 0.125f;
        }
    }
}

extern "C" void kernel_launch(void* const* d_in, const int* in_sizes, int n_in,
                              void* d_out, int out_size) {
    const float* time_seq = (const float*)d_in[0];
    const float* dt_seq   = (const float*)d_in[1];
    const int*   ev_w     = (const int*)  d_in[2];
    const float* exp_raw  = (const float*)d_in[3];
    const float* unif     = (const float*)d_in[4];
    const float* emb      = (const float*)d_in[5];
    const float* scale    = (const float*)d_in[6];
    const float* bias     = (const float*)d_in[7];

    const int n_rows    = in_sizes[0];          // B*S = 16384
    const int res_elems = n_rows * NSAMP;
    float* res  = (float*)d_out;
    float* wout = res + res_elems;
    const int write_w = (out_size >= 2 * res_elems) ? 1 : 0;

    table_kernel<<<(NEV * NTAB) / 256, 256>>>(emb, scale, bias);

    // sampler overlaps its preamble with the table build via PDL.
    cudaLaunchConfig_t cfg = {};
    cfg.gridDim  = dim3((unsigned)n_rows, 1, 1);
    cfg.blockDim = dim3(64, 1, 1);
    cfg.dynamicSmemBytes = 0;
    cfg.stream = 0;
    cudaLaunchAttribute attr[1];
    attr[0].id = cudaLaunchAttributeProgrammaticStreamSerialization;
    attr[0].val.programmaticStreamSerializationAllowed = 1;
    cfg.attrs = attr;
    cfg.numAttrs = 1;
    cudaLaunchKernelEx(&cfg, sampler_kernel,
                       time_seq, dt_seq, ev_w, exp_raw, unif,
                       res, wout, write_w);
}

// round 15
// speedup vs baseline: 1.5112x; 1.5112x over previous
#include <cuda_runtime.h>
#include <math.h>
#include <stdint.h>

#define NSAMP  8
#define NEXP   256
#define NMARK  10
#define KBOUND 40
#define NEV    20
#define NTAB   2048

// overlapped-pair table: g_tab[ev][i] = { f(c_i), f(c_{i+1}) },  c_i = -1 + i*h
__device__ float2 g_tab[NEV * NTAB];   // 327 KB, L2-resident

// cos with explicit Cody-Waite reduction by 2*pi, then MUFU cos.
__device__ __forceinline__ float cos_cw(float t) {
    const float INV2PI   = 0.15915494309189535f;
    const float TWOPI_HI = 6.2831854820251465f;
    const float TWOPI_LO = -1.7484555e-07f;
    float k = rintf(t * INV2PI);
    float r = fmaf(-k, TWOPI_HI, t);
    r = fmaf(-k, TWOPI_LO, r);
    return __cosf(r);
}

// exact-path sum_m softplus (table build only)
__device__ __forceinline__ float total_intensity_reg(float c,
                                                     const float* __restrict__ c0,
                                                     const float* __restrict__ sc) {
    float lin = 0.0f, prod = 1.0f;
#pragma unroll
    for (int m = 0; m < NMARK; m++) {
        float x = fmaf(sc[m], c, c0[m]);
        lin += fmaxf(x, 0.0f);
        prod *= (1.0f + __expf(-fabsf(x)));
    }
    return lin + __logf(prod);
}

// table lookup with linear interpolation; c in [-1,1]
__device__ __forceinline__ float total_lookup(float c, const float2* __restrict__ tab) {
    float idx_f = (c + 1.0f) * ((float)(NTAB - 1) * 0.5f);
    int   i     = (int)idx_f;
    i = max(0, min(i, NTAB - 2));
    float frac  = idx_f - (float)i;
    float2 p = tab[i];
    return fmaf(frac, p.y - p.x, p.x);
}

// detect int64 vs int32 encoding of event_seq, return event id for `row`.
__device__ __forceinline__ int load_event(const int* __restrict__ ev_w,
                                          int row, int lane) {
    int a = 0;
    if (lane < NMARK) a = ev_w[2 * lane + 1] | ev_w[2 * (lane + NMARK) + 1];
    unsigned ball = __ballot_sync(0xffffffffu, a != 0);
    return (ball == 0u) ? ev_w[2 * row] : ev_w[row];
}

// ---- kernel T: build intensity table for all 20 event types ----
__global__ void __launch_bounds__(256) table_kernel(
    const float* __restrict__ emb,
    const float* __restrict__ scale,
    const float* __restrict__ bias)
{
    const int idx = blockIdx.x * 256 + threadIdx.x;   // 20*2048 entries
    const int ev  = idx / NTAB;
    const int i   = idx % NTAB;

    float c0[NMARK], sc[NMARK];
#pragma unroll
    for (int m = 0; m < NMARK; m++) {
        c0[m] = emb[ev * NMARK + m] + bias[m];
        sc[m] = scale[m];
    }
    const float h   = 2.0f / (float)(NTAB - 1);
    const float c0f = fmaf((float)i, h, -1.0f);
    const int   i1  = (i + 1 < NTAB) ? i + 1 : i;
    const float c1f = fmaf((float)i1, h, -1.0f);

    float2 v;
    v.x = total_intensity_reg(c0f, c0, sc);
    v.y = total_intensity_reg(c1f, c0, sc);
    g_tab[idx] = v;

    __threadfence();
    cudaTriggerProgrammaticLaunchCompletion();
}

// ---- sampler: 64-thread blocks, 32/SM, direct-LDG phase 2 (R12 base) ----
__global__ void __launch_bounds__(64, 28) sampler_kernel(
    const float* __restrict__ time_seq,
    const float* __restrict__ dt_seq,
    const int*   __restrict__ ev_w,
    const float* __restrict__ exp_raw,
    const float* __restrict__ unif,
    float* __restrict__ out_res,
    float* __restrict__ out_w,
    int write_w)
{
    const int row  = blockIdx.x;
    const int tid  = threadIdx.x;   // 0..63
    const int lane = tid & 31;
    const int warp = tid >> 5;      // 0..1

    __shared__ __align__(16) float s_exr[NEXP];
    __shared__ __align__(16) float s_tot[NEXP];

    // ======== PDL preamble: independent of the table ========
    // thread t owns candidates 4t..4t+3 (one coalesced streaming LDG.128)
    const float4 ex4 = __ldcs((const float4*)(exp_raw + (size_t)row * NEXP) + tid);
    const float t0  = time_seq[row];
    const float dtv = dt_seq[row];
    const int   ev  = load_event(ev_w, row, lane);
    const float2* tab = g_tab + ev * NTAB;
    ((float4*)s_exr)[tid] = ex4;

    // ======== wait for table kernel ========
    cudaGridDependencySynchronize();

    // ---- boundary upper bound, computed redundantly per warp (no barrier) ----
    float lam = total_lookup(cos_cw(fmaf(dtv, (float)lane * (1.0f / 39.0f), t0)), tab);
    if (lane < KBOUND - 32)
        lam = fmaxf(lam, total_lookup(
            cos_cw(fmaf(dtv, (float)(lane + 32) * (1.0f / 39.0f), t0)), tab));
#pragma unroll
    for (int o = 16; o; o >>= 1)
        lam = fmaxf(lam, __shfl_xor_sync(0xffffffffu, lam, o));
    const float upper = 1.5f * lam;   // OVER_SAMPLE_RATE; identical in both warps

    // ---- phase 1: 4 candidates per thread via table ----
    float4 tot4;
    tot4.x = total_lookup(cos_cw(t0 + __fdividef(ex4.x, upper)), tab);
    tot4.y = total_lookup(cos_cw(t0 + __fdividef(ex4.y, upper)), tab);
    tot4.z = total_lookup(cos_cw(t0 + __fdividef(ex4.z, upper)), tab);
    tot4.w = total_lookup(cos_cw(t0 + __fdividef(ex4.w, upper)), tab);
    ((float4*)s_tot)[tid] = tot4;

    __syncthreads();   // the only block barrier

    // ---- phase 2: warp w owns slots 4w..4w+3 ----
    // per-lane mins for all 4 slots FIRST (LDGs pipeline across slots),
    // shuffle reductions deferred to the end (4 independent trees interleave).
    const float4* pe = (const float4*)s_exr;
    const float4* pt = (const float4*)s_tot;
    const float*  ubase = unif + (size_t)row * (NSAMP * NEXP);
    float mloc[4];
#pragma unroll
    for (int js = 0; js < 4; js++) {
        const int j = warp * 4 + js;
        const float4* su = (const float4*)(ubase + (size_t)j * NEXP);
        float m = INFINITY;
#pragma unroll
        for (int half = 0; half < 2; half++) {
            int q = 32 * half + lane;
            float4 u4 = __ldcs(su + q);   // streaming LDG.128, coalesced
            float4 e4 = pe[q];
            float4 t4 = pt[q];
            if (u4.x * upper < t4.x) m = fminf(m, e4.x);
            if (u4.y * upper < t4.y) m = fminf(m, e4.y);
            if (u4.z * upper < t4.z) m = fminf(m, e4.z);
            if (u4.w * upper < t4.w) m = fminf(m, e4.w);
        }
        mloc[js] = m;
    }
#pragma unroll
    for (int js = 0; js < 4; js++) {
#pragma unroll
        for (int o = 16; o; o >>= 1)
            mloc[js] = fminf(mloc[js], __shfl_xor_sync(0xffffffffu, mloc[js], o));
    }
    if (lane == 0) {
        float4 rr;
        rr.x = isinf(mloc[0]) ? 5.0f : fminf(__fdividef(mloc[0], upper), 1e5f);
        rr.y = isinf(mloc[1]) ? 5.0f : fminf(__fdividef(mloc[1], upper), 1e5f);
        rr.z = isinf(mloc[2]) ? 5.0f : fminf(__fdividef(mloc[2], upper), 1e5f);
        rr.w = isinf(mloc[3]) ? 5.0f : fminf(__fdividef(mloc[3], upper), 1e5f);
        // row*8 + warp*4 floats => 16B-aligned: one STG.128
        *(float4*)(out_res + (size_t)row * NSAMP + warp * 4) = rr;
        if (write_w) {
            float4 ww = make_float4(0.125f, 0.125f, 0.125f, 0.125f);
            *(float4*)(out_w + (size_t)row * NSAMP + warp * 4) = ww;
        }
    }
}

extern "C" void kernel_launch(void* const* d_in, const int* in_sizes, int n_in,
                              void* d_out, int out_size) {
    const float* time_seq = (const float*)d_in[0];
    const float* dt_seq   = (const float*)d_in[1];
    const int*   ev_w     = (const int*)  d_in[2];
    const float* exp_raw  = (const float*)d_in[3];
    const float* unif     = (const float*)d_in[4];
    const float* emb      = (const float*)d_in[5];
    const float* scale    = (const float*)d_in[6];
    const float* bias     = (const float*)d_in[7];

    const int n_rows    = in_sizes[0];          // B*S = 16384
    const int res_elems = n_rows * NSAMP;
    float* res  = (float*)d_out;
    float* wout = res + res_elems;
    const int write_w = (out_size >= 2 * res_elems) ? 1 : 0;

    table_kernel<<<(NEV * NTAB) / 256, 256>>>(emb, scale, bias);

    // sampler overlaps its preamble with the table build via PDL.
    cudaLaunchConfig_t cfg = {};
    cfg.gridDim  = dim3((unsigned)n_rows, 1, 1);
    cfg.blockDim = dim3(64, 1, 1);
    cfg.dynamicSmemBytes = 0;
    cfg.stream = 0;
    cudaLaunchAttribute attr[1];
    attr[0].id = cudaLaunchAttributeProgrammaticStreamSerialization;
    attr[0].val.programmaticStreamSerializationAllowed = 1;
    cfg.attrs = attr;
    cfg.numAttrs = 1;
    cudaLaunchKernelEx(&cfg, sampler_kernel,
                       time_seq, dt_seq, ev_w, exp_raw, unif,
                       res, wout, write_w);
}

// round 16
// speedup vs baseline: 1.5236x; 1.0082x over previous
#include <cuda_runtime.h>
#include <math.h>
#include <stdint.h>

#define NSAMP  8
#define NEXP   256
#define NMARK  10
#define KBOUND 40
#define NEV    20
#define NTAB   2048

// overlapped-pair table: g_tab[ev][i] = { f(c_i), f(c_{i+1}) },  c_i = -1 + i*h
__device__ float2 g_tab[NEV * NTAB];   // 327 KB, L2-resident

// cos with explicit Cody-Waite reduction by 2*pi, then MUFU cos.
__device__ __forceinline__ float cos_cw(float t) {
    const float INV2PI   = 0.15915494309189535f;
    const float TWOPI_HI = 6.2831854820251465f;
    const float TWOPI_LO = -1.7484555e-07f;
    float k = rintf(t * INV2PI);
    float r = fmaf(-k, TWOPI_HI, t);
    r = fmaf(-k, TWOPI_LO, r);
    return __cosf(r);
}

// exact-path sum_m softplus (table build only)
__device__ __forceinline__ float total_intensity_reg(float c,
                                                     const float* __restrict__ c0,
                                                     const float* __restrict__ sc) {
    float lin = 0.0f, prod = 1.0f;
#pragma unroll
    for (int m = 0; m < NMARK; m++) {
        float x = fmaf(sc[m], c, c0[m]);
        lin += fmaxf(x, 0.0f);
        prod *= (1.0f + __expf(-fabsf(x)));
    }
    return lin + __logf(prod);
}

// table lookup with linear interpolation; c in [-1,1]
__device__ __forceinline__ float total_lookup(float c, const float2* __restrict__ tab) {
    float idx_f = (c + 1.0f) * ((float)(NTAB - 1) * 0.5f);
    int   i     = (int)idx_f;
    i = max(0, min(i, NTAB - 2));
    float frac  = idx_f - (float)i;
    float2 p = tab[i];
    return fmaf(frac, p.y - p.x, p.x);
}

// detect int64 vs int32 encoding of event_seq, return event id for `row`.
__device__ __forceinline__ int load_event(const int* __restrict__ ev_w,
                                          int row, int lane) {
    int a = 0;
    if (lane < NMARK) a = ev_w[2 * lane + 1] | ev_w[2 * (lane + NMARK) + 1];
    unsigned ball = __ballot_sync(0xffffffffu, a != 0);
    return (ball == 0u) ? ev_w[2 * row] : ev_w[row];
}

// ---- kernel T: build intensity table for all 20 event types ----
__global__ void __launch_bounds__(256) table_kernel(
    const float* __restrict__ emb,
    const float* __restrict__ scale,
    const float* __restrict__ bias)
{
    const int idx = blockIdx.x * 256 + threadIdx.x;   // 20*2048 entries
    const int ev  = idx / NTAB;
    const int i   = idx % NTAB;

    float c0[NMARK], sc[NMARK];
#pragma unroll
    for (int m = 0; m < NMARK; m++) {
        c0[m] = emb[ev * NMARK + m] + bias[m];
        sc[m] = scale[m];
    }
    const float h   = 2.0f / (float)(NTAB - 1);
    const float c0f = fmaf((float)i, h, -1.0f);
    const int   i1  = (i + 1 < NTAB) ? i + 1 : i;
    const float c1f = fmaf((float)i1, h, -1.0f);

    float2 v;
    v.x = total_intensity_reg(c0f, c0, sc);
    v.y = total_intensity_reg(c1f, c0, sc);
    g_tab[idx] = v;

    __threadfence();
    cudaTriggerProgrammaticLaunchCompletion();
}

// ---- sampler: 64-thr blocks; ALL unif loads register-prefetched at entry ----
__global__ void __launch_bounds__(64, 16) sampler_kernel(
    const float* __restrict__ time_seq,
    const float* __restrict__ dt_seq,
    const int*   __restrict__ ev_w,
    const float* __restrict__ exp_raw,
    const float* __restrict__ unif,
    float* __restrict__ out_res,
    float* __restrict__ out_w,
    int write_w)
{
    const int row  = blockIdx.x;
    const int tid  = threadIdx.x;   // 0..63
    const int lane = tid & 31;
    const int warp = tid >> 5;      // 0..1

    __shared__ __align__(16) float s_exr[NEXP];
    __shared__ __align__(16) float s_tot[NEXP];

    // ======== PDL preamble: 9 independent LDG.128 in flight from cycle 0 ====
    // warp w owns slots 4w..4w+3; u[2*js+half] = slot (4w+js), quarter q=32*half+lane
    const float*  ubase = unif + (size_t)row * (NSAMP * NEXP) + (size_t)warp * 4 * NEXP;
    float4 u[8];
#pragma unroll
    for (int js = 0; js < 4; js++) {
        const float4* su = (const float4*)(ubase + js * NEXP);
        u[2 * js]     = __ldcs(su + lane);
        u[2 * js + 1] = __ldcs(su + 32 + lane);
    }
    // thread t owns candidates 4t..4t+3 (one coalesced streaming LDG.128)
    const float4 ex4 = __ldcs((const float4*)(exp_raw + (size_t)row * NEXP) + tid);
    const float t0  = time_seq[row];
    const float dtv = dt_seq[row];
    const int   ev  = load_event(ev_w, row, lane);
    const float2* tab = g_tab + ev * NTAB;
    ((float4*)s_exr)[tid] = ex4;

    // ======== wait for table kernel ========
    cudaGridDependencySynchronize();

    // ---- boundary upper bound, computed redundantly per warp (no barrier) ----
    float lam = total_lookup(cos_cw(fmaf(dtv, (float)lane * (1.0f / 39.0f), t0)), tab);
    if (lane < KBOUND - 32)
        lam = fmaxf(lam, total_lookup(
            cos_cw(fmaf(dtv, (float)(lane + 32) * (1.0f / 39.0f), t0)), tab));
#pragma unroll
    for (int o = 16; o; o >>= 1)
        lam = fmaxf(lam, __shfl_xor_sync(0xffffffffu, lam, o));
    const float upper = 1.5f * lam;   // OVER_SAMPLE_RATE; identical in both warps

    // ---- phase 1: 4 candidates per thread via table ----
    float4 tot4;
    tot4.x = total_lookup(cos_cw(t0 + __fdividef(ex4.x, upper)), tab);
    tot4.y = total_lookup(cos_cw(t0 + __fdividef(ex4.y, upper)), tab);
    tot4.z = total_lookup(cos_cw(t0 + __fdividef(ex4.z, upper)), tab);
    tot4.w = total_lookup(cos_cw(t0 + __fdividef(ex4.w, upper)), tab);
    ((float4*)s_tot)[tid] = tot4;

    __syncthreads();   // the only block barrier

    // ---- phase 2: consume prefetched u registers; mins first, shuffles last ----
    const float4* pe = (const float4*)s_exr;
    const float4* pt = (const float4*)s_tot;
    float mloc[4];
#pragma unroll
    for (int js = 0; js < 4; js++) {
        float m = INFINITY;
#pragma unroll
        for (int half = 0; half < 2; half++) {
            int q = 32 * half + lane;
            float4 u4 = u[2 * js + half];
            float4 e4 = pe[q];
            float4 t4 = pt[q];
            if (u4.x * upper < t4.x) m = fminf(m, e4.x);
            if (u4.y * upper < t4.y) m = fminf(m, e4.y);
            if (u4.z * upper < t4.z) m = fminf(m, e4.z);
            if (u4.w * upper < t4.w) m = fminf(m, e4.w);
        }
        mloc[js] = m;
    }
#pragma unroll
    for (int js = 0; js < 4; js++) {
#pragma unroll
        for (int o = 16; o; o >>= 1)
            mloc[js] = fminf(mloc[js], __shfl_xor_sync(0xffffffffu, mloc[js], o));
    }
    if (lane == 0) {
        float4 rr;
        rr.x = isinf(mloc[0]) ? 5.0f : fminf(__fdividef(mloc[0], upper), 1e5f);
        rr.y = isinf(mloc[1]) ? 5.0f : fminf(__fdividef(mloc[1], upper), 1e5f);
        rr.z = isinf(mloc[2]) ? 5.0f : fminf(__fdividef(mloc[2], upper), 1e5f);
        rr.w = isinf(mloc[3]) ? 5.0f : fminf(__fdividef(mloc[3], upper), 1e5f);
        *(float4*)(out_res + (size_t)row * NSAMP + warp * 4) = rr;
        if (write_w) {
            float4 ww = make_float4(0.125f, 0.125f, 0.125f, 0.125f);
            *(float4*)(out_w + (size_t)row * NSAMP + warp * 4) = ww;
        }
    }
}

extern "C" void kernel_launch(void* const* d_in, const int* in_sizes, int n_in,
                              void* d_out, int out_size) {
    const float* time_seq = (const float*)d_in[0];
    const float* dt_seq   = (const float*)d_in[1];
    const int*   ev_w     = (const int*)  d_in[2];
    const float* exp_raw  = (const float*)d_in[3];
    const float* unif     = (const float*)d_in[4];
    const float* emb      = (const float*)d_in[5];
    const float* scale    = (const float*)d_in[6];
    const float* bias     = (const float*)d_in[7];

    const int n_rows    = in_sizes[0];          // B*S = 16384
    const int res_elems = n_rows * NSAMP;
    float* res  = (float*)d_out;
    float* wout = res + res_elems;
    const int write_w = (out_size >= 2 * res_elems) ? 1 : 0;

    table_kernel<<<(NEV * NTAB) / 256, 256>>>(emb, scale, bias);

    // sampler overlaps its preamble (9 LDG.128 per warp) with the table build.
    cudaLaunchConfig_t cfg = {};
    cfg.gridDim  = dim3((unsigned)n_rows, 1, 1);
    cfg.blockDim = dim3(64, 1, 1);
    cfg.dynamicSmemBytes = 0;
    cfg.stream = 0;
    cudaLaunchAttribute attr[1];
    attr[0].id = cudaLaunchAttributeProgrammaticStreamSerialization;
    attr[0].val.programmaticStreamSerializationAllowed = 1;
    cfg.attrs = attr;
    cfg.numAttrs = 1;
    cudaLaunchKernelEx(&cfg, sampler_kernel,
                       time_seq, dt_seq, ev_w, exp_raw, unif,
                       res, wout, write_w);
}